// round 11
// baseline (speedup 1.0000x reference)
#include <cuda_runtime.h>
#include <cstdint>
#include <cstddef>

// AlarmworkRNN reduced form: only state row SEQ-1 (2047) reaches the output,
// so the scan collapses to a 256-step recurrence on two 1024-vectors.
//
// R11 = packet exchange (16B single-copy-atomic {z1,z2,0,tag}, proven R9/R10)
// restructured for overlap:
//  - single verified-load phase: spin on packet 0 only, verify-load the rest
//    (selective retry; no sentinel round, no flood)
//  - next-step packet loads + x prefetch + out matvec issued AFTER publish,
//    overlapping other CTAs' production
//  - layer-2 dot precomputed on odd steps (z2 is held), balancing parities
//  - 4-way FMA accumulators (short dependency chains)
// Weights register-resident (R8-proven). Monotonic tags, replay-safe.

#define ND   256
#define SEQ  2048
#define NI   256
#define NH   1024
#define NO   256
#define GRID 128
#define TPB  256
#define H_PER 8
#define O_PER 2
#define PAD  9          // staging transpose pad (conflict-free)
#define CPT  4          // packets per thread (1024/256)

// Publication k lives in buffer k&1. Packet: {z1_bits, z2_bits, 0, tag}.
__device__ uint4 g_pub[2][NH];    // zero-init; tags monotonic across replays

__device__ __forceinline__ uint4 ldv4(const uint4* p) {
    uint4 v;
    asm volatile("ld.volatile.global.v4.u32 {%0,%1,%2,%3}, [%4];"
                 : "=r"(v.x), "=r"(v.y), "=r"(v.z), "=r"(v.w)
                 : "l"(p) : "memory");
    return v;
}
__device__ __forceinline__ void stv4(uint4* p, uint4 v) {
    asm volatile("st.volatile.global.v4.u32 [%0], {%1,%2,%3,%4};"
                 :: "l"(p), "r"(v.x), "r"(v.y), "r"(v.z), "r"(v.w) : "memory");
}

__device__ __forceinline__ float warp_reduce(float a) {
    #pragma unroll
    for (int off = 16; off; off >>= 1)
        a += __shfl_xor_sync(0xffffffffu, a, off);
    return a;
}

extern __shared__ float smem[];
// floats: stg[9216] z12s[1024] z2s[1024] z1s[1024] xs[256]
#define OFF_STG  0
#define OFF_Z12  9216
#define OFF_Z2   10240
#define OFF_Z1   11264
#define OFF_XS   12288
#define SMEM_FLOATS 12544

__global__ void __launch_bounds__(TPB, 1)
rnn_kernel(const float* __restrict__ x,
           const float* __restrict__ W_in1, const float* __restrict__ b_in1,
           const float* __restrict__ W_rec1,
           const float* __restrict__ W_in2, const float* __restrict__ b_in2,
           const float* __restrict__ W_rec2,
           const float* __restrict__ W_out, const float* __restrict__ b_out,
           float* __restrict__ out) {
    float* stg  = smem + OFF_STG;
    float* z12s = smem + OFF_Z12;
    float* z2s  = smem + OFF_Z2;
    float* z1s  = smem + OFF_Z1;
    float* xs   = smem + OFF_XS;

    const int tid   = threadIdx.x;
    const int cta   = blockIdx.x;
    const int w     = tid >> 5;
    const int lane  = tid & 31;
    const int jbase = cta * H_PER;
    const int kbase = cta * O_PER;
    const int c0    = tid * CPT;          // this thread's packet columns

    // Launch-entry tag base: buffer-0 tags are uniform across columns/CTAs.
    const unsigned base = ldv4(&g_pub[0][0]).w;

    // ---- Stage weights into REGISTERS via padded SMEM transpose (R8-verbatim) ----
    float wrec1[32], wrec2[32], win1[8], win2[8], wout[32];

    for (int r = tid >> 3; r < NH; r += 32)                 // W_rec1
        stg[r * PAD + (tid & 7)] = W_rec1[r * NH + jbase + (tid & 7)];
    __syncthreads();
    #pragma unroll
    for (int i = 0; i < 32; i++)
        wrec1[i] = stg[(lane + 32 * i) * PAD + w];
    __syncthreads();

    for (int r = tid >> 3; r < NH; r += 32)                 // W_rec2
        stg[r * PAD + (tid & 7)] = W_rec2[r * NH + jbase + (tid & 7)];
    __syncthreads();
    #pragma unroll
    for (int i = 0; i < 32; i++)
        wrec2[i] = stg[(lane + 32 * i) * PAD + w];
    __syncthreads();

    for (int r = tid >> 3; r < NI; r += 32)                 // W_in1
        stg[r * PAD + (tid & 7)] = W_in1[r * NH + jbase + (tid & 7)];
    __syncthreads();
    #pragma unroll
    for (int i = 0; i < 8; i++)
        win1[i] = stg[(lane + 32 * i) * PAD + w];
    __syncthreads();

    for (int r = tid >> 3; r < NI; r += 32)                 // W_in2
        stg[r * PAD + (tid & 7)] = W_in2[r * NH + jbase + (tid & 7)];
    __syncthreads();
    #pragma unroll
    for (int i = 0; i < 8; i++)
        win2[i] = stg[(lane + 32 * i) * PAD + w];
    __syncthreads();

    for (int r = tid >> 1; r < NH; r += 128)                // W_out (2 cols)
        stg[r * PAD + (tid & 1)] = W_out[r * NO + kbase + (tid & 1)];
    __syncthreads();
    if (w >= 6) {
        #pragma unroll
        for (int i = 0; i < 32; i++)
            wout[i] = stg[(lane + 32 * i) * PAD + (w - 6)];
    }

    const float b1 = b_in1[jbase + w];
    const float b2 = b_in2[jbase + w];
    const float bo = (w >= 6) ? b_out[kbase + (w - 6)] : 0.f;

    float z2reg = 0.f;    // warp-uniform: z2 value of column jbase+w
    float a2pre = 0.f;    // stashed layer-2 partial (computed on odd t)

    // ---- Iteration 0: compute pub 1 from zero state, publish packets ----
    for (int i = tid; i < NH; i += TPB) { z12s[i] = 0.f; z2s[i] = 0.f; }
    xs[tid] = x[(size_t)(SEQ - 1) * NI + tid];          // x row 0
    __syncthreads();
    {
        float a1 = 0.f, a2 = 0.f;
        #pragma unroll
        for (int i = 0; i < 8; i++) {
            const float xv = xs[lane + 32 * i];
            a1 = fmaf(win1[i], xv, a1);
            a2 = fmaf(win2[i], xv, a2);
        }
        // recurrent parts are zero (initial state)
        a1 = warp_reduce(a1);
        a2 = warp_reduce(a2);
        const float z1n = tanhf(a1 + b1);
        z2reg = tanhf(a2 + b2);
        if (lane == 0) {          // publish pub 1 -> buffer 1, tag base+1
            uint4 pkt;
            pkt.x = __float_as_uint(z1n);
            pkt.y = __float_as_uint(z2reg);
            pkt.z = 0u;
            pkt.w = base + 1u;
            stv4(&g_pub[1][jbase + w], pkt);
        }
    }

    // Pre-issue loads for t=1 (buffer 1) + x prefetch.
    uint4 v0 = ldv4(&g_pub[1][c0 + 0]);
    uint4 v1 = ldv4(&g_pub[1][c0 + 1]);
    uint4 v2 = ldv4(&g_pub[1][c0 + 2]);
    uint4 v3 = ldv4(&g_pub[1][c0 + 3]);
    float xpref = __ldg(&x[((size_t)1 * SEQ + (SEQ - 1)) * NI + tid]);
    __syncthreads();   // iteration-0 smem reads complete before overwrite

    // ---- Iterations 1..ND: verify pub t -> SMEM -> compute pub t+1 ----
    for (int t = 1; t <= ND; t++) {
        const int cb   = t & 1;
        const int nbuf = cb ^ 1;
        const bool ev  = ((t & 1) == 0);
        const unsigned target = base + (unsigned)t;
        const uint4* pb = &g_pub[cb][c0];

        // Finalize pre-issued loads; selective retry (packet0 is the gate --
        // same producer CTA writes all 4 of this thread's columns).
        while ((int)(v0.w - target) < 0) v0 = ldv4(pb + 0);
        while ((int)(v1.w - target) < 0) v1 = ldv4(pb + 1);
        while ((int)(v2.w - target) < 0) v2 = ldv4(pb + 2);
        while ((int)(v3.w - target) < 0) v3 = ldv4(pb + 3);

        {
            const float p0 = __uint_as_float(v0.x), q0 = __uint_as_float(v0.y);
            const float p1 = __uint_as_float(v1.x), q1 = __uint_as_float(v1.y);
            const float p2 = __uint_as_float(v2.x), q2 = __uint_as_float(v2.y);
            const float p3 = __uint_as_float(v3.x), q3 = __uint_as_float(v3.y);
            z1s [c0 + 0] = p0; z2s[c0 + 0] = q0; z12s[c0 + 0] = p0 + q0;
            z1s [c0 + 1] = p1; z2s[c0 + 1] = q1; z12s[c0 + 1] = p1 + q1;
            z1s [c0 + 2] = p2; z2s[c0 + 2] = q2; z12s[c0 + 2] = p2 + q2;
            z1s [c0 + 3] = p3; z2s[c0 + 3] = q3; z12s[c0 + 3] = p3 + q3;
        }
        xs[tid] = xpref;
        __syncthreads();   // SYNC1: state staged for compute

        if (t < ND) {
            // Layer 1: 8 x-FMAs + 32 rec-FMAs, 4 accumulators.
            float s0 = 0.f, s1 = 0.f, s2 = 0.f, s3 = 0.f;
            #pragma unroll
            for (int i = 0; i < 8; i += 4) {
                s0 = fmaf(win1[i + 0], xs[lane + 32 * (i + 0)], s0);
                s1 = fmaf(win1[i + 1], xs[lane + 32 * (i + 1)], s1);
                s2 = fmaf(win1[i + 2], xs[lane + 32 * (i + 2)], s2);
                s3 = fmaf(win1[i + 3], xs[lane + 32 * (i + 3)], s3);
            }
            #pragma unroll
            for (int i = 0; i < 32; i += 4) {
                s0 = fmaf(wrec1[i + 0], z12s[lane + 32 * (i + 0)], s0);
                s1 = fmaf(wrec1[i + 1], z12s[lane + 32 * (i + 1)], s1);
                s2 = fmaf(wrec1[i + 2], z12s[lane + 32 * (i + 2)], s2);
                s3 = fmaf(wrec1[i + 3], z12s[lane + 32 * (i + 3)], s3);
            }
            float a1 = (s0 + s1) + (s2 + s3);

            float z1n, a2 = 0.f;
            if (ev) {
                // Even: layer-2 = stashed rec-partial + x part only.
                a2 = a2pre;
                #pragma unroll
                for (int i = 0; i < 8; i++)
                    a2 = fmaf(win2[i], xs[lane + 32 * i], a2);
                a1 = warp_reduce(a1);
                a2 = warp_reduce(a2);
                z1n = tanhf(a1 + b1);
                z2reg = tanhf(a2 + b2);
            } else {
                // Odd: precompute next even step's z2 rec-partial (z2 held).
                float r0 = 0.f, r1 = 0.f, r2 = 0.f, r3 = 0.f;
                #pragma unroll
                for (int i = 0; i < 32; i += 4) {
                    r0 = fmaf(wrec2[i + 0], z2s[lane + 32 * (i + 0)], r0);
                    r1 = fmaf(wrec2[i + 1], z2s[lane + 32 * (i + 1)], r1);
                    r2 = fmaf(wrec2[i + 2], z2s[lane + 32 * (i + 2)], r2);
                    r3 = fmaf(wrec2[i + 3], z2s[lane + 32 * (i + 3)], r3);
                }
                a2pre = (r0 + r1) + (r2 + r3);
                a1 = warp_reduce(a1);
                z1n = tanhf(a1 + b1);
            }

            if (lane == 0) {      // publish pub t+1 (single 128-bit packet)
                uint4 pkt;
                pkt.x = __float_as_uint(z1n);
                pkt.y = __float_as_uint(z2reg);   // odd t: republish held z2
                pkt.z = 0u;
                pkt.w = target + 1u;
                stv4(&g_pub[nbuf][jbase + w], pkt);
            }

            // Pre-issue next iteration's packet loads (fly during out/x work).
            const uint4* nb = &g_pub[nbuf][c0];
            v0 = ldv4(nb + 0);
            v1 = ldv4(nb + 1);
            v2 = ldv4(nb + 2);
            v3 = ldv4(nb + 3);
            if (t + 1 < ND)
                xpref = __ldg(&x[((size_t)(t + 1) * SEQ + (SEQ - 1)) * NI + tid]);
        }

        // out[t-1] = tanh(z1(pub t) . Wout + bo) -- overlapped, off chain.
        if (w >= 6) {
            float a = 0.f;
            #pragma unroll
            for (int i = 0; i < 32; i++)
                a = fmaf(wout[i], z1s[lane + 32 * i], a);
            a = warp_reduce(a);
            if (lane == 0)
                out[(size_t)(t - 1) * NO + kbase + (w - 6)] = tanhf(a + bo);
        }
        __syncthreads();   // SYNC2: z1s/xs reads done before next overwrite
    }
}

extern "C" void kernel_launch(void* const* d_in, const int* in_sizes, int n_in,
                              void* d_out, int out_size) {
    const float* x      = (const float*)d_in[0];
    const float* W_in1  = (const float*)d_in[1];
    const float* b_in1  = (const float*)d_in[2];
    const float* W_rec1 = (const float*)d_in[3];
    const float* W_in2  = (const float*)d_in[4];
    const float* b_in2  = (const float*)d_in[5];
    const float* W_rec2 = (const float*)d_in[6];
    const float* W_out  = (const float*)d_in[7];
    const float* b_out  = (const float*)d_in[8];
    float* out = (float*)d_out;

    const size_t shmem = SMEM_FLOATS * sizeof(float);
    cudaFuncSetAttribute(rnn_kernel, cudaFuncAttributeMaxDynamicSharedMemorySize,
                         (int)shmem);
    rnn_kernel<<<GRID, TPB, shmem>>>(x, W_in1, b_in1, W_rec1,
                                     W_in2, b_in2, W_rec2, W_out, b_out, out);
}

// round 12
// speedup vs baseline: 1.8032x; 1.8032x over previous
#include <cuda_runtime.h>
#include <cstdint>
#include <cstddef>

// AlarmworkRNN reduced form: only state row SEQ-1 (2047) reaches the output,
// so the scan collapses to a 256-step recurrence on two 1024-vectors.
//
// R12 = R8 protocol VERBATIM (atomicExch flag + volatile poll by threads
// 0..127 + gated float4 bulk load -- best measured, 697us) with local-chain
// cuts only:
//  1. packed publish: res staged in SMEM, warp0 lanes 0-7 store 3x32B
//     coalesced, then lane0 fence+flag (fence drains 3 sectors, not 24)
//  2. parity balance: z2.Wrec2 partial precomputed on odd steps (z2 held);
//     z2s loaded on odd steps only
//  3. 4-way FMA accumulators
// Weights register-resident (R8-proven staging). Monotonic flags, replay-safe.

#define ND   256
#define SEQ  2048
#define NI   256
#define NH   1024
#define NO   256
#define GRID 128
#define TPB  256
#define H_PER 8
#define O_PER 2
#define TAGS 8          // slot stride in unsigned (32B sector spacing)
#define PAD  9          // staging transpose pad (conflict-free)

__device__ unsigned g_slot[GRID * TAGS];   // zero-init; monotonic across replays
// Publication k lives in buffer k&1.
__device__ float g_z1 [2][NH];
__device__ float g_z2 [2][NH];
__device__ float g_z12[2][NH];

__device__ __forceinline__ float warp_reduce(float a) {
    #pragma unroll
    for (int off = 16; off; off >>= 1)
        a += __shfl_xor_sync(0xffffffffu, a, off);
    return a;
}

extern __shared__ float smem[];
// floats: stg[9216] z12s[1024] z2s[1024] zout[1024] xs[256] res1[8] res2[8]
#define OFF_STG  0
#define OFF_Z12  9216
#define OFF_Z2   10240
#define OFF_ZO   11264
#define OFF_XS   12288
#define OFF_R1   12544
#define OFF_R2   12552
#define SMEM_FLOATS 12560

__global__ void __launch_bounds__(TPB, 1)
rnn_kernel(const float* __restrict__ x,
           const float* __restrict__ W_in1, const float* __restrict__ b_in1,
           const float* __restrict__ W_rec1,
           const float* __restrict__ W_in2, const float* __restrict__ b_in2,
           const float* __restrict__ W_rec2,
           const float* __restrict__ W_out, const float* __restrict__ b_out,
           float* __restrict__ out) {
    float* stg  = smem + OFF_STG;
    float* z12s = smem + OFF_Z12;
    float* z2s  = smem + OFF_Z2;
    float* zout = smem + OFF_ZO;
    float* xs   = smem + OFF_XS;
    float* res1 = smem + OFF_R1;
    float* res2 = smem + OFF_R2;

    const int tid   = threadIdx.x;
    const int cta   = blockIdx.x;
    const int w     = tid >> 5;
    const int lane  = tid & 31;
    const int jbase = cta * H_PER;
    const int kbase = cta * O_PER;

    // Flag base (uniform across CTAs: each publishes exactly ND flags/launch).
    const unsigned base = atomicAdd(&g_slot[cta * TAGS], 0u);

    // ---- Stage weights into REGISTERS via padded SMEM transpose (R8-verbatim) ----
    float wrec1[32], wrec2[32], win1[8], win2[8], wout[32];

    for (int r = tid >> 3; r < NH; r += 32)                 // W_rec1
        stg[r * PAD + (tid & 7)] = W_rec1[r * NH + jbase + (tid & 7)];
    __syncthreads();
    #pragma unroll
    for (int i = 0; i < 32; i++)
        wrec1[i] = stg[(lane + 32 * i) * PAD + w];
    __syncthreads();

    for (int r = tid >> 3; r < NH; r += 32)                 // W_rec2
        stg[r * PAD + (tid & 7)] = W_rec2[r * NH + jbase + (tid & 7)];
    __syncthreads();
    #pragma unroll
    for (int i = 0; i < 32; i++)
        wrec2[i] = stg[(lane + 32 * i) * PAD + w];
    __syncthreads();

    for (int r = tid >> 3; r < NI; r += 32)                 // W_in1
        stg[r * PAD + (tid & 7)] = W_in1[r * NH + jbase + (tid & 7)];
    __syncthreads();
    #pragma unroll
    for (int i = 0; i < 8; i++)
        win1[i] = stg[(lane + 32 * i) * PAD + w];
    __syncthreads();

    for (int r = tid >> 3; r < NI; r += 32)                 // W_in2
        stg[r * PAD + (tid & 7)] = W_in2[r * NH + jbase + (tid & 7)];
    __syncthreads();
    #pragma unroll
    for (int i = 0; i < 8; i++)
        win2[i] = stg[(lane + 32 * i) * PAD + w];
    __syncthreads();

    for (int r = tid >> 1; r < NH; r += 128)                // W_out (2 cols)
        stg[r * PAD + (tid & 1)] = W_out[r * NO + kbase + (tid & 1)];
    __syncthreads();
    if (w >= 6) {
        #pragma unroll
        for (int i = 0; i < 32; i++)
            wout[i] = stg[(lane + 32 * i) * PAD + (w - 6)];
    }

    const float b1 = b_in1[jbase + w];
    const float b2 = b_in2[jbase + w];
    const float bo = (w >= 6) ? b_out[kbase + (w - 6)] : 0.f;

    float z2reg = 0.f;    // warp-uniform: z2 value of column jbase+w
    float a2pre = 0.f;    // per-lane partial of z2.Wrec2 (computed on odd t)

    // ---- Iteration 0: compute pub 1 (zero recurrent state) -> res SMEM ----
    xs[tid] = x[(size_t)(SEQ - 1) * NI + tid];          // x row 0
    __syncthreads();
    {
        float a1 = 0.f, a2 = 0.f;
        #pragma unroll
        for (int i = 0; i < 8; i++) {
            const float xv = xs[lane + 32 * i];
            a1 = fmaf(win1[i], xv, a1);
            a2 = fmaf(win2[i], xv, a2);
        }
        a1 = warp_reduce(a1);
        a2 = warp_reduce(a2);
        const float z1n = tanhf(a1 + b1);
        z2reg = tanhf(a2 + b2);
        if (lane == 0) { res1[w] = z1n; res2[w] = z2reg; }
    }

    float xpref = __ldg(&x[((size_t)1 * SEQ + (SEQ - 1)) * NI + tid]);  // row 1

    // ---- Iterations 1..ND: publish pub t -> poll -> load pub t -> compute ----
    for (int t = 1; t <= ND; t++) {
        const int cb  = t & 1;            // buffer for pub t
        const bool ev = ((t & 1) == 0);
        const unsigned target = base + (unsigned)t;

        __syncthreads();                  // res complete; prior smem reads done

        // Phase A: packed publish (warp 0) | poll (warps 0-3) | out (warps 6-7)
        if (w == 0) {
            if (lane < 8) {
                const float r1 = res1[lane];
                const float r2 = res2[lane];
                g_z1 [cb][jbase + lane] = r1;       // 32B coalesced
                g_z2 [cb][jbase + lane] = r2;       // 32B coalesced
                g_z12[cb][jbase + lane] = r1 + r2;  // 32B coalesced
            }
            __syncwarp();
            if (lane == 0) {
                __threadfence();                     // 3 sectors to drain
                atomicExch(&g_slot[cta * TAGS], target);
            }
        }
        if (tid < GRID) {
            volatile unsigned* sp = &g_slot[tid * TAGS];
            while ((int)(*sp - target) < 0) { }
            __threadfence();              // acquire: flag before data reads
        } else if (w >= 6 && t >= 2) {
            // out[t-2] = tanh(z1(pub t-1) . Wout + bo) from stashed zout.
            float a = 0.f;
            #pragma unroll
            for (int i = 0; i < 32; i++)
                a = fmaf(wout[i], zout[lane + 32 * i], a);
            a = warp_reduce(a);
            if (lane == 0)
                out[(size_t)(t - 2) * NO + kbase + (w - 6)] = tanhf(a + bo);
        }
        __syncthreads();   // pub t visible grid-wide; zout readers done

        // Phase B: gated bulk load of pub t (float4, R8-verbatim pattern).
        ((float4*)z12s)[tid] = ((const float4*)g_z12[cb])[tid];
        ((float4*)zout)[tid] = ((const float4*)g_z1 [cb])[tid];
        if (!ev)                          // odd t: z2 needed for precompute
            ((float4*)z2s)[tid] = ((const float4*)g_z2[cb])[tid];
        xs[tid] = xpref;
        __syncthreads();

        // Phase C: compute pub t+1 -> res SMEM.
        if (t < ND) {
            float s0 = 0.f, s1 = 0.f, s2 = 0.f, s3 = 0.f;
            #pragma unroll
            for (int i = 0; i < 8; i += 4) {
                s0 = fmaf(win1[i + 0], xs[lane + 32 * (i + 0)], s0);
                s1 = fmaf(win1[i + 1], xs[lane + 32 * (i + 1)], s1);
                s2 = fmaf(win1[i + 2], xs[lane + 32 * (i + 2)], s2);
                s3 = fmaf(win1[i + 3], xs[lane + 32 * (i + 3)], s3);
            }
            #pragma unroll
            for (int i = 0; i < 32; i += 4) {
                s0 = fmaf(wrec1[i + 0], z12s[lane + 32 * (i + 0)], s0);
                s1 = fmaf(wrec1[i + 1], z12s[lane + 32 * (i + 1)], s1);
                s2 = fmaf(wrec1[i + 2], z12s[lane + 32 * (i + 2)], s2);
                s3 = fmaf(wrec1[i + 3], z12s[lane + 32 * (i + 3)], s3);
            }
            float a1 = (s0 + s1) + (s2 + s3);

            float z1n;
            if (ev) {
                // Even: layer-2 = stashed rec partial + x part (8 FMAs).
                float a2 = a2pre;
                #pragma unroll
                for (int i = 0; i < 8; i++)
                    a2 = fmaf(win2[i], xs[lane + 32 * i], a2);
                a1 = warp_reduce(a1);
                a2 = warp_reduce(a2);
                z1n = tanhf(a1 + b1);
                z2reg = tanhf(a2 + b2);
            } else {
                // Odd: z2 held; precompute rec partial for next even step.
                float r0 = 0.f, r1_ = 0.f, r2_ = 0.f, r3_ = 0.f;
                #pragma unroll
                for (int i = 0; i < 32; i += 4) {
                    r0  = fmaf(wrec2[i + 0], z2s[lane + 32 * (i + 0)], r0);
                    r1_ = fmaf(wrec2[i + 1], z2s[lane + 32 * (i + 1)], r1_);
                    r2_ = fmaf(wrec2[i + 2], z2s[lane + 32 * (i + 2)], r2_);
                    r3_ = fmaf(wrec2[i + 3], z2s[lane + 32 * (i + 3)], r3_);
                }
                a2pre = (r0 + r1_) + (r2_ + r3_);
                a1 = warp_reduce(a1);
                z1n = tanhf(a1 + b1);
            }
            if (lane == 0) { res1[w] = z1n; res2[w] = z2reg; }

            // Prefetch x row t+1 (latency hidden behind next poll window).
            if (t + 1 < ND)
                xpref = __ldg(&x[((size_t)(t + 1) * SEQ + (SEQ - 1)) * NI + tid]);
        }
    }

    // ---- Tail: out[ND-1] from pub ND (zout loaded at t=ND) ----
    if (w >= 6) {
        float a = 0.f;
        #pragma unroll
        for (int i = 0; i < 32; i++)
            a = fmaf(wout[i], zout[lane + 32 * i], a);
        a = warp_reduce(a);
        if (lane == 0)
            out[(size_t)(ND - 1) * NO + kbase + (w - 6)] = tanhf(a + bo);
    }
}

extern "C" void kernel_launch(void* const* d_in, const int* in_sizes, int n_in,
                              void* d_out, int out_size) {
    const float* x      = (const float*)d_in[0];
    const float* W_in1  = (const float*)d_in[1];
    const float* b_in1  = (const float*)d_in[2];
    const float* W_rec1 = (const float*)d_in[3];
    const float* W_in2  = (const float*)d_in[4];
    const float* b_in2  = (const float*)d_in[5];
    const float* W_rec2 = (const float*)d_in[6];
    const float* W_out  = (const float*)d_in[7];
    const float* b_out  = (const float*)d_in[8];
    float* out = (float*)d_out;

    const size_t shmem = SMEM_FLOATS * sizeof(float);
    cudaFuncSetAttribute(rnn_kernel, cudaFuncAttributeMaxDynamicSharedMemorySize,
                         (int)shmem);
    rnn_kernel<<<GRID, TPB, shmem>>>(x, W_in1, b_in1, W_rec1,
                                     W_in2, b_in2, W_rec2, W_out, b_out, out);
}